// round 10
// baseline (speedup 1.0000x reference)
#include <cuda_runtime.h>
#include <cuda_bf16.h>
#include <math.h>
#include <stdint.h>

#define Dm      768
#define NH      12
#define DH      64
#define BATCH   2
#define SEQ     2048
#define M_TOT   (BATCH * SEQ)   // 4096

// ---------------------------------------------------------------------------
// scratch (allocation-free rule: __device__ globals)
// ---------------------------------------------------------------------------
static __device__ __nv_bfloat16 g_inh[3][M_TOT * Dm];  // raw q,k,v hi/lo
static __device__ __nv_bfloat16 g_inl[3][M_TOT * Dm];
static __device__ __nv_bfloat16 g_wh[4][Dm * Dm];      // wq,wk,wv,wo hi/lo
static __device__ __nv_bfloat16 g_wl[4][Dm * Dm];
static __device__ __nv_bfloat16 g_ah[3][M_TOT * Dm];   // projected Q,K,V hi/lo
static __device__ __nv_bfloat16 g_al[3][M_TOT * Dm];   // (Q pre-scaled log2e/8)
static __device__ __nv_bfloat16 g_ch[M_TOT * Dm];      // ctx hi/lo
static __device__ __nv_bfloat16 g_cl[M_TOT * Dm];

// ---------------------------------------------------------------------------
// helpers
// ---------------------------------------------------------------------------
__device__ __forceinline__ uint32_t smem_to_u32(const void* p) {
    uint32_t a;
    asm("{ .reg .u64 t; cvta.to.shared.u64 t, %1; cvt.u32.u64 %0, t; }"
        : "=r"(a) : "l"(p));
    return a;
}
__device__ __forceinline__ void cp16(uint32_t dst, const void* src) {
    asm volatile("cp.async.cg.shared.global [%0], [%1], 16;"
        :: "r"(dst), "l"(src));
}
#define CP_COMMIT() asm volatile("cp.async.commit_group;" ::: "memory")
#define CP_WAIT(n)  asm volatile("cp.async.wait_group %0;" :: "n"(n) : "memory")

__device__ __forceinline__ void ldsm_x4(uint32_t* r, uint32_t addr) {
    asm volatile("ldmatrix.sync.aligned.m8n8.x4.shared.b16 {%0,%1,%2,%3}, [%4];"
        : "=r"(r[0]), "=r"(r[1]), "=r"(r[2]), "=r"(r[3]) : "r"(addr));
}
__device__ __forceinline__ void ldsm_x4_t(uint32_t* r, uint32_t addr) {
    asm volatile("ldmatrix.sync.aligned.m8n8.x4.trans.shared.b16 {%0,%1,%2,%3}, [%4];"
        : "=r"(r[0]), "=r"(r[1]), "=r"(r[2]), "=r"(r[3]) : "r"(addr));
}
__device__ __forceinline__ void mma_bf16(float* d, const uint32_t* a, const uint32_t* b) {
    asm volatile("mma.sync.aligned.m16n8k16.row.col.f32.bf16.bf16.f32 "
        "{%0,%1,%2,%3}, {%4,%5,%6,%7}, {%8,%9}, {%0,%1,%2,%3};"
        : "+f"(d[0]), "+f"(d[1]), "+f"(d[2]), "+f"(d[3])
        : "r"(a[0]), "r"(a[1]), "r"(a[2]), "r"(a[3]), "r"(b[0]), "r"(b[1]));
}
__device__ __forceinline__ float fexp2(float x) {
    float t = x + 12582912.0f;
    int   n = __float_as_int(t) - 0x4B400000;
    float f = x - (t - 12582912.0f);
    float p = 0.00133335581f;
    p = fmaf(p, f, 0.00961812911f);
    p = fmaf(p, f, 0.0555041087f);
    p = fmaf(p, f, 0.240226507f);
    p = fmaf(p, f, 0.693147182f);
    p = fmaf(p, f, 1.0f);
    return __int_as_float(__float_as_int(p) + (n << 23));
}
__device__ __forceinline__ uint32_t packbf(float a, float b) {
    __nv_bfloat162 t = __float22bfloat162_rn(make_float2(a, b));
    return *(uint32_t*)&t;
}
__device__ __forceinline__
void store_split2(__nv_bfloat16* Hi, __nv_bfloat16* Lo, size_t idx,
                  float x, float y) {
    __nv_bfloat16 hx = __float2bfloat16(x), hy = __float2bfloat16(y);
    *(__nv_bfloat162*)(Hi + idx) = __nv_bfloat162(hx, hy);
    __nv_bfloat16 lx = __float2bfloat16(x - __bfloat162float(hx));
    __nv_bfloat16 ly = __float2bfloat16(y - __bfloat162float(hy));
    *(__nv_bfloat162*)(Lo + idx) = __nv_bfloat162(lx, ly);
}

// ---------------------------------------------------------------------------
// elementwise fp32 -> bf16 hi/lo split (inputs z=0..2, weights z=3..6)
// ---------------------------------------------------------------------------
struct SplitArgs {
    const float* src[7];
    __nv_bfloat16* hi[7];
    __nv_bfloat16* lo[7];
    int nelem[7];
};

__global__ __launch_bounds__(256)
void split_all(SplitArgs a)
{
    const int z = blockIdx.z;
    const int i = (blockIdx.x * 256 + threadIdx.x) * 4;
    if (i >= a.nelem[z]) return;
    float4 v = *(const float4*)(a.src[z] + i);
    store_split2(a.hi[z], a.lo[z], i,     v.x, v.y);
    store_split2(a.hi[z], a.lo[z], i + 2, v.z, v.w);
}

// ---------------------------------------------------------------------------
// tensor-core GEMM: 256 thr / 8 warps (4m x 2n grid, warp tile m32 x n64),
// CTA tile 128x128, BK=64, 3-stage cp.async pipeline, SINGLE sync per stage,
// B-fragment double buffering.  Coalesced loaders (R9-verified).
// Stage layout (69632B):
//   Ah@0     : 128 rows x 128B data, 144B stride (pad -> conflict-free ldsm)
//   Al@18432 : same
//   Bh@36864 : 64 rows x 256B, chunk xor (row&7) swizzle
//   Bl@53248 : same
// ---------------------------------------------------------------------------
#define GSTAGE      69632
#define GSMEM_BYTES (3 * GSTAGE)   // 204KB -> 1 CTA/SM

struct TCArgs {
    const __nv_bfloat16* Ah[3];
    const __nv_bfloat16* Al[3];
    const __nv_bfloat16* Bh[3];
    const __nv_bfloat16* Bl[3];
    const float* bias[3];
    float scale[3];
    float* Cf[3];             // fp32 output if non-null
    __nv_bfloat16* Ch[3];     // else split output
    __nv_bfloat16* Cl[3];
};

__device__ __forceinline__
void gemm_issue_stage(uint32_t sb, int stage,
                      const __nv_bfloat16* Ah, const __nv_bfloat16* Al,
                      const __nv_bfloat16* Bh, const __nv_bfloat16* Bl,
                      int m0, int n0, int k0, int t)
{
    const uint32_t st = sb + stage * GSTAGE;
    {   // A: 8 threads per row (1 line per 8 threads), 4 passes
        const int c  = t & 7;
        const int r0 = t >> 3;             // 0..31
#pragma unroll
        for (int p = 0; p < 4; ++p) {
            const int row = r0 + 32 * p;
            const size_t g = (size_t)(m0 + row) * Dm + k0 + c * 8;
            cp16(st + row * 144 + c * 16,         Ah + g);
            cp16(st + 18432 + row * 144 + c * 16, Al + g);
        }
    }
    {   // B: 16 threads per row (2 lines per 16 threads), 4 passes
        const int c  = t & 15;
        const int r0 = t >> 4;             // 0..15
#pragma unroll
        for (int p = 0; p < 4; ++p) {
            const int row = r0 + 16 * p;
            const size_t g = (size_t)(k0 + row) * Dm + n0 + c * 8;
            const uint32_t d = st + 36864 + row * 256 + (((c ^ (row & 7))) << 4);
            cp16(d,         Bh + g);
            cp16(d + 16384, Bl + g);
        }
    }
    CP_COMMIT();
}

__global__ __launch_bounds__(256)
void tc_gemm(TCArgs a)
{
    extern __shared__ char sm[];
    const uint32_t sb = smem_to_u32(sm);

    const int z  = blockIdx.z;
    const int m0 = blockIdx.y * 128;
    const int n0 = blockIdx.x * 128;
    const int t  = threadIdx.x;
    const int w  = t >> 5;
    const int l  = t & 31;
    const int lg = l >> 3, li = l & 7;
    const int gr = l >> 2, gc = l & 3;
    const int mw  = (w & 3) * 32;       // warp m offset (4 warps in m)
    const int nw8 = (w >> 2) * 8;       // warp n offset in n8 units (2 in n)

    const __nv_bfloat16* Ah = a.Ah[z];
    const __nv_bfloat16* Al = a.Al[z];
    const __nv_bfloat16* Bh = a.Bh[z];
    const __nv_bfloat16* Bl = a.Bl[z];

    float acc[2][8][4];
#pragma unroll
    for (int mi = 0; mi < 2; ++mi)
#pragma unroll
        for (int nj = 0; nj < 8; ++nj)
#pragma unroll
            for (int c = 0; c < 4; ++c) acc[mi][nj][c] = 0.0f;

    const int NS = Dm / 64;   // 12
    gemm_issue_stage(sb, 0, Ah, Al, Bh, Bl, m0, n0, 0,  t);
    gemm_issue_stage(sb, 1, Ah, Al, Bh, Bl, m0, n0, 64, t);

    int stage = 0;
    for (int s = 0; s < NS; ++s) {
        if (s + 1 < NS) { CP_WAIT(1); } else { CP_WAIT(0); }
        __syncthreads();   // single barrier: stage s ready AND stage s-1 consumed

        if (s + 2 < NS) {
            int nst = stage + 2; if (nst >= 3) nst -= 3;
            gemm_issue_stage(sb, nst, Ah, Al, Bh, Bl, m0, n0, (s + 2) * 64, t);
        }

        const uint32_t st = sb + stage * GSTAGE;

        // A fragments: 2 m16 x 4 k16, hi+lo (144B stride, no swizzle)
        uint32_t afh[2][4][4], afl[2][4][4];
#pragma unroll
        for (int mi = 0; mi < 2; ++mi) {
            const int row = mw + mi * 16 + (lg & 1) * 8 + li;
#pragma unroll
            for (int ks = 0; ks < 4; ++ks) {
                const int c = ks * 2 + (lg >> 1);
                const uint32_t ad = st + row * 144 + c * 16;
                ldsm_x4(afh[mi][ks], ad);
                ldsm_x4(afl[mi][ks], ad + 18432);
            }
        }

        // B fragments double-buffered over nj
        uint32_t bfh[2][2][4], bfl[2][2][4];
        {
            const int krow0 = lg * 8 + li;
            const int krow1 = 32 + lg * 8 + li;
            const int c = nw8;
            const uint32_t ad0 = st + 36864 + krow0 * 256 + (((c ^ (krow0 & 7))) << 4);
            const uint32_t ad1 = st + 36864 + krow1 * 256 + (((c ^ (krow1 & 7))) << 4);
            ldsm_x4_t(bfh[0][0], ad0); ldsm_x4_t(bfl[0][0], ad0 + 16384);
            ldsm_x4_t(bfh[0][1], ad1); ldsm_x4_t(bfl[0][1], ad1 + 16384);
        }

#pragma unroll
        for (int nj = 0; nj < 8; ++nj) {
            const int cb = nj & 1;
            if (nj < 7) {
                const int nb = cb ^ 1;
                const int c = nw8 + nj + 1;
                const int krow0 = lg * 8 + li;
                const int krow1 = 32 + lg * 8 + li;
                const uint32_t ad0 = st + 36864 + krow0 * 256 + (((c ^ (krow0 & 7))) << 4);
                const uint32_t ad1 = st + 36864 + krow1 * 256 + (((c ^ (krow1 & 7))) << 4);
                ldsm_x4_t(bfh[nb][0], ad0); ldsm_x4_t(bfl[nb][0], ad0 + 16384);
                ldsm_x4_t(bfh[nb][1], ad1); ldsm_x4_t(bfl[nb][1], ad1 + 16384);
            }
#pragma unroll
            for (int mi = 0; mi < 2; ++mi)
#pragma unroll
                for (int ks = 0; ks < 4; ++ks) {
                    const uint32_t* b2h = bfh[cb][ks >> 1] + 2 * (ks & 1);
                    const uint32_t* b2l = bfl[cb][ks >> 1] + 2 * (ks & 1);
                    mma_bf16(acc[mi][nj], afh[mi][ks], b2h);
                    mma_bf16(acc[mi][nj], afl[mi][ks], b2h);
                    mma_bf16(acc[mi][nj], afh[mi][ks], b2l);
                }
        }
        if (++stage == 3) stage = 0;
    }

    // epilogue
    const float* bias = a.bias[z];
    const float  scl  = a.scale[z];
    float* Cf = a.Cf[z];
    __nv_bfloat16* Ch = a.Ch[z];
    __nv_bfloat16* Cl = a.Cl[z];

#pragma unroll
    for (int mi = 0; mi < 2; ++mi) {
        const int row0 = m0 + mw + mi * 16 + gr;
#pragma unroll
        for (int nj = 0; nj < 8; ++nj) {
            const int col = n0 + (nw8 + nj) * 8 + gc * 2;
            const float b0 = bias[col], b1 = bias[col + 1];
            const float v00 = (acc[mi][nj][0] + b0) * scl;
            const float v01 = (acc[mi][nj][1] + b1) * scl;
            const float v10 = (acc[mi][nj][2] + b0) * scl;
            const float v11 = (acc[mi][nj][3] + b1) * scl;
            if (Cf) {
                *(float2*)&Cf[(size_t)row0 * Dm + col]       = make_float2(v00, v01);
                *(float2*)&Cf[(size_t)(row0 + 8) * Dm + col] = make_float2(v10, v11);
            } else {
                store_split2(Ch, Cl, (size_t)row0 * Dm + col,       v00, v01);
                store_split2(Ch, Cl, (size_t)(row0 + 8) * Dm + col, v10, v11);
            }
        }
    }
}

// ---------------------------------------------------------------------------
// mma.sync flash attention: BM=128 queries, 4 warps (m32 each), BN=64,
// cp.async 2-stage K/V pipeline, SINGLE sync per tile, 2 CTAs/SM.
// Stage layout (32KB): Kh@0, Kl@8192, Vh@16384, Vl@24576; stage1 at +32768.
// ---------------------------------------------------------------------------
#define AT_SMEM_BYTES (2 * 32768)

__device__ __forceinline__
void attn_issue_tile(uint32_t dst, const __nv_bfloat16* src, int row0, int t)
{
    const int c  = t & 7;
    const int r0 = t >> 3;   // 0..15
#pragma unroll
    for (int p = 0; p < 4; ++p) {
        const int row = r0 + 16 * p;
        cp16(dst + row * 128 + (((c ^ (row & 7))) << 4),
             src + (size_t)(row0 + row) * Dm + c * 8);
    }
}

__global__ __launch_bounds__(128, 2)
void attn_mma()
{
    extern __shared__ char sm[];
    const uint32_t sb = smem_to_u32(sm);

    const int t  = threadIdx.x;
    const int w  = t >> 5;
    const int l  = t & 31;
    const int lg = l >> 3;
    const int li = l & 7;
    const int gr = l >> 2;
    const int gc = l & 3;

    const int bh = blockIdx.y;
    const int b  = bh / NH;
    const int h  = bh % NH;
    const int q0 = blockIdx.x * 128;

    const size_t hb = (size_t)b * SEQ * Dm + h * DH;
    const __nv_bfloat16* Qh = g_ah[0] + hb;
    const __nv_bfloat16* Ql = g_al[0] + hb;
    const __nv_bfloat16* Kh = g_ah[1] + hb;
    const __nv_bfloat16* Kl = g_al[1] + hb;
    const __nv_bfloat16* Vh = g_ah[2] + hb;
    const __nv_bfloat16* Vl = g_al[2] + hb;

    // ---- stage Q tile (128 rows x 64 bf16, hi+lo = 32KB) through stage 0 ----
    {
        const int c  = t & 7;
        const int r0 = t >> 3;   // 0..15
#pragma unroll
        for (int p = 0; p < 8; ++p) {
            const int row = r0 + 16 * p;
            const size_t g = (size_t)(q0 + row) * Dm + c * 8;
            const uint32_t d = sb + row * 128 + (((c ^ (row & 7))) << 4);
            cp16(d,         Qh + g);
            cp16(d + 16384, Ql + g);
        }
    }
    CP_COMMIT();
    CP_WAIT(0);
    __syncthreads();

    uint32_t qfh[2][4][4], qfl[2][4][4];   // [mi][ks][4]
#pragma unroll
    for (int mi = 0; mi < 2; ++mi) {
        const int row = w * 32 + mi * 16 + (lg & 1) * 8 + li;
        const int rs  = row & 7;
#pragma unroll
        for (int ks = 0; ks < 4; ++ks) {
            const int chunk = ks * 2 + (lg >> 1);
            const uint32_t a = sb + row * 128 + (((chunk ^ rs)) << 4);
            ldsm_x4(qfh[mi][ks], a);
            ldsm_x4(qfl[mi][ks], a + 16384);
        }
    }
    __syncthreads();   // Q frags read before KV tile 0 overwrites stage 0

    // prefetch KV tile 0 into stage 0
    attn_issue_tile(sb,         Kh, 0, t);
    attn_issue_tile(sb + 8192,  Kl, 0, t);
    attn_issue_tile(sb + 16384, Vh, 0, t);
    attn_issue_tile(sb + 24576, Vl, 0, t);
    CP_COMMIT();

    float O[2][8][4];
#pragma unroll
    for (int mi = 0; mi < 2; ++mi)
#pragma unroll
        for (int i = 0; i < 8; ++i)
#pragma unroll
            for (int j = 0; j < 4; ++j) O[mi][i][j] = 0.0f;
    float lsumA[2] = {0.f, 0.f}, lsumB[2] = {0.f, 0.f};

    const int NT = SEQ / 64;   // 32

    for (int kt = 0; kt < NT; ++kt) {
        const int cur = kt & 1;
        CP_WAIT(0);          // tile kt complete (only outstanding group)
        __syncthreads();     // single barrier: data visible AND tile kt-1 consumed

        if (kt + 1 < NT) {   // issue next tile; overlaps with compute below
            const uint32_t nst = sb + (cur ^ 1) * 32768;
            const int r0 = (kt + 1) * 64;
            attn_issue_tile(nst,         Kh, r0, t);
            attn_issue_tile(nst + 8192,  Kl, r0, t);
            attn_issue_tile(nst + 16384, Vh, r0, t);
            attn_issue_tile(nst + 24576, Vl, r0, t);
            CP_COMMIT();
        }

        const uint32_t st = sb + cur * 32768;

        // ---- S = Q @ K^T for both m16 halves (K frags shared) ----
        float S[2][8][4];
#pragma unroll
        for (int mi = 0; mi < 2; ++mi)
#pragma unroll
            for (int i = 0; i < 8; ++i)
#pragma unroll
                for (int j = 0; j < 4; ++j) S[mi][i][j] = 0.0f;

#pragma unroll
        for (int j = 0; j < 8; ++j) {
            const int krow = 8 * j + li;
            const int ksw  = krow & 7;
#pragma unroll
            for (int kh = 0; kh < 2; ++kh) {
                uint32_t bfh[4], bfl[4];
                const uint32_t addr =
                    st + krow * 128 + ((((kh * 4 + lg) ^ ksw)) << 4);
                ldsm_x4(bfh, addr);
                ldsm_x4(bfl, addr + 8192);
#pragma unroll
                for (int k2 = 0; k2 < 2; ++k2) {
                    const int ks = kh * 2 + k2;
#pragma unroll
                    for (int mi = 0; mi < 2; ++mi) {
                        mma_bf16(S[mi][j], qfh[mi][ks], bfh + 2 * k2);
                        mma_bf16(S[mi][j], qfh[mi][ks], bfl + 2 * k2);
                        mma_bf16(S[mi][j], qfl[mi][ks], bfh + 2 * k2);
                    }
                }
            }
        }

        // ---- P = exp2(S), pack A-fragments hi/lo ----
        uint32_t pfh[2][4][4], pfl[2][4][4];
#pragma unroll
        for (int mi = 0; mi < 2; ++mi) {
#pragma unroll
            for (int j2 = 0; j2 < 4; ++j2) {
                float* c0 = S[mi][2 * j2];
                float* c1 = S[mi][2 * j2 + 1];
                float e00 = fexp2(c0[0]), e01 = fexp2(c0[1]);
                float e02 = fexp2(c0[2]), e03 = fexp2(c0[3]);
                float e10 = fexp2(c1[0]), e11 = fexp2(c1[1]);
                float e12 = fexp2(c1[2]), e13 = fexp2(c1[3]);
                lsumA[mi] += (e00 + e01) + (e10 + e11);
                lsumB[mi] += (e02 + e03) + (e12 + e13);

                pfh[mi][j2][0] = packbf(e00, e01);
                pfh[mi][j2][1] = packbf(e02, e03);
                pfh[mi][j2][2] = packbf(e10, e11);
                pfh[mi][j2][3] = packbf(e12, e13);

                float h00 = __bfloat162float(__float2bfloat16(e00));
                float h01 = __bfloat162float(__float2bfloat16(e01));
                float h02 = __bfloat162float(__float2bfloat16(e02));
                float h03 = __bfloat162float(__float2bfloat16(e03));
                float h10 = __bfloat162float(__float2bfloat16(e10));
                float h11 = __bfloat162float(__float2bfloat16(e11));
                float h12 = __bfloat162float(__float2bfloat16(e12));
                float h13 = __bfloat162float(__float2bfloat16(e13));
                pfl[mi][j2][0] = packbf(e00 - h00, e01 - h01);
                pfl[mi][j2][1] = packbf(e02 - h02, e03 - h03);
                pfl[mi][j2][2] = packbf(e10 - h10, e11 - h11);
                pfl[mi][j2][3] = packbf(e12 - h12, e13 - h13);
            }
        }

        // ---- O += P @ V (V frags shared across both m16 halves) ----
#pragma unroll
        for (int nj = 0; nj < 8; ++nj) {
#pragma unroll
            for (int khf = 0; khf < 2; ++khf) {
                const int key = khf * 32 + lg * 8 + li;
                const uint32_t addr =
                    st + 16384 + key * 128 + (((nj ^ (key & 7))) << 4);
                uint32_t vfh[4], vfl[4];
                ldsm_x4_t(vfh, addr);
                ldsm_x4_t(vfl, addr + 8192);
#pragma unroll
                for (int k2 = 0; k2 < 2; ++k2) {
                    const int j2 = khf * 2 + k2;
#pragma unroll
                    for (int mi = 0; mi < 2; ++mi) {
                        mma_bf16(O[mi][nj], pfh[mi][j2], vfh + 2 * k2);
                        mma_bf16(O[mi][nj], pfl[mi][j2], vfh + 2 * k2);
                        mma_bf16(O[mi][nj], pfh[mi][j2], vfl + 2 * k2);
                    }
                }
            }
        }
    }

    // ---- normalize & store (ctx as bf16 hi/lo) ----
#pragma unroll
    for (int mi = 0; mi < 2; ++mi) {
        lsumA[mi] += __shfl_xor_sync(0xffffffffu, lsumA[mi], 1);
        lsumA[mi] += __shfl_xor_sync(0xffffffffu, lsumA[mi], 2);
        lsumB[mi] += __shfl_xor_sync(0xffffffffu, lsumB[mi], 1);
        lsumB[mi] += __shfl_xor_sync(0xffffffffu, lsumB[mi], 2);
        const float invA = 1.0f / lsumA[mi];
        const float invB = 1.0f / lsumB[mi];

        const int rowA = b * SEQ + q0 + w * 32 + mi * 16 + gr;
        const int colb = h * DH + gc * 2;
#pragma unroll
        for (int nj = 0; nj < 8; ++nj) {
            const int col = colb + nj * 8;
            store_split2(g_ch, g_cl, (size_t)rowA * Dm + col,
                         O[mi][nj][0] * invA, O[mi][nj][1] * invA);
            store_split2(g_ch, g_cl, (size_t)(rowA + 8) * Dm + col,
                         O[mi][nj][2] * invB, O[mi][nj][3] * invB);
        }
    }
}

// ---------------------------------------------------------------------------
// launch
// ---------------------------------------------------------------------------
extern "C" void kernel_launch(void* const* d_in, const int* in_sizes, int n_in,
                              void* d_out, int out_size)
{
    const float* v  = (const float*)d_in[0];
    const float* k  = (const float*)d_in[1];
    const float* q  = (const float*)d_in[2];
    const float* wq = (const float*)d_in[3];
    const float* bq = (const float*)d_in[4];
    const float* wk = (const float*)d_in[5];
    const float* bk = (const float*)d_in[6];
    const float* wv = (const float*)d_in[7];
    const float* bv = (const float*)d_in[8];
    const float* wo = (const float*)d_in[9];
    const float* bo = (const float*)d_in[10];
    float* out = (float*)d_out;

    __nv_bfloat16 *inh, *inl, *wh, *wl, *ah, *al, *ch, *cl;
    cudaGetSymbolAddress((void**)&inh, g_inh);
    cudaGetSymbolAddress((void**)&inl, g_inl);
    cudaGetSymbolAddress((void**)&wh,  g_wh);
    cudaGetSymbolAddress((void**)&wl,  g_wl);
    cudaGetSymbolAddress((void**)&ah,  g_ah);
    cudaGetSymbolAddress((void**)&al,  g_al);
    cudaGetSymbolAddress((void**)&ch,  g_ch);
    cudaGetSymbolAddress((void**)&cl,  g_cl);

    cudaFuncSetAttribute(tc_gemm,
                         cudaFuncAttributeMaxDynamicSharedMemorySize,
                         GSMEM_BYTES);
    cudaFuncSetAttribute(attn_mma,
                         cudaFuncAttributeMaxDynamicSharedMemorySize,
                         AT_SMEM_BYTES);

    const int ISZ = M_TOT * Dm;   // 3145728
    const int WSZ = Dm * Dm;      // 589824
    const float SCLQ = 0.18033688011112042f;   // log2(e)/8

    // 1) split inputs (q,k,v) and weights to bf16 hi/lo
    SplitArgs sa;
    sa.src[0] = q;  sa.hi[0] = inh + 0 * (size_t)ISZ; sa.lo[0] = inl + 0 * (size_t)ISZ; sa.nelem[0] = ISZ;
    sa.src[1] = k;  sa.hi[1] = inh + 1 * (size_t)ISZ; sa.lo[1] = inl + 1 * (size_t)ISZ; sa.nelem[1] = ISZ;
    sa.src[2] = v;  sa.hi[2] = inh + 2 * (size_t)ISZ; sa.lo[2] = inl + 2 * (size_t)ISZ; sa.nelem[2] = ISZ;
    sa.src[3] = wq; sa.hi[3] = wh + 0 * (size_t)WSZ;  sa.lo[3] = wl + 0 * (size_t)WSZ;  sa.nelem[3] = WSZ;
    sa.src[4] = wk; sa.hi[4] = wh + 1 * (size_t)WSZ;  sa.lo[4] = wl + 1 * (size_t)WSZ;  sa.nelem[4] = WSZ;
    sa.src[5] = wv; sa.hi[5] = wh + 2 * (size_t)WSZ;  sa.lo[5] = wl + 2 * (size_t)WSZ;  sa.nelem[5] = WSZ;
    sa.src[6] = wo; sa.hi[6] = wh + 3 * (size_t)WSZ;  sa.lo[6] = wl + 3 * (size_t)WSZ;  sa.nelem[6] = WSZ;
    split_all<<<dim3(ISZ / 1024, 1, 7), 256>>>(sa);

    // 2) QKV projections (tensor cores, split epilogue)
    TCArgs ga;
    for (int z = 0; z < 3; ++z) {
        ga.Ah[z] = inh + (size_t)z * ISZ;  ga.Al[z] = inl + (size_t)z * ISZ;
        ga.Bh[z] = wh + (size_t)z * WSZ;   ga.Bl[z] = wl + (size_t)z * WSZ;
        ga.Cf[z] = nullptr;
        ga.Ch[z] = ah + (size_t)z * ISZ;   ga.Cl[z] = al + (size_t)z * ISZ;
    }
    ga.bias[0] = bq; ga.bias[1] = bk; ga.bias[2] = bv;
    ga.scale[0] = SCLQ; ga.scale[1] = 1.0f; ga.scale[2] = 1.0f;
    tc_gemm<<<dim3(Dm / 128, M_TOT / 128, 3), 256, GSMEM_BYTES>>>(ga);

    // 3) attention (BM=128)
    attn_mma<<<dim3(SEQ / 128, BATCH * NH), 128, AT_SMEM_BYTES>>>();

    // 4) output projection -> fp32 d_out
    TCArgs go;
    for (int z = 0; z < 3; ++z) {
        go.Ah[z] = ch; go.Al[z] = cl;
        go.Bh[z] = wh + 3 * (size_t)WSZ; go.Bl[z] = wl + 3 * (size_t)WSZ;
        go.bias[z] = bo; go.scale[z] = 1.0f;
        go.Cf[z] = out; go.Ch[z] = nullptr; go.Cl[z] = nullptr;
    }
    tc_gemm<<<dim3(Dm / 128, M_TOT / 128, 1), 256, GSMEM_BYTES>>>(go);
}

// round 11
// speedup vs baseline: 1.4002x; 1.4002x over previous
#include <cuda_runtime.h>
#include <cuda_fp16.h>
#include <math.h>
#include <stdint.h>

#define Dm      768
#define NH      12
#define DH      64
#define BATCH   2
#define SEQ     2048
#define M_TOT   (BATCH * SEQ)   // 4096

// ---------------------------------------------------------------------------
// scratch (allocation-free rule: __device__ globals)
// fp16 hi/lo representation; B-side operands (weights, K, V) keep hi ONLY.
// ---------------------------------------------------------------------------
static __device__ __half g_inh[3][M_TOT * Dm];  // raw q,k,v hi
static __device__ __half g_inl[3][M_TOT * Dm];  // raw q,k,v lo
static __device__ __half g_wh[4][Dm * Dm];      // wq,wk,wv,wo hi (no lo!)
static __device__ __half g_ah[3][M_TOT * Dm];   // projected Q,K,V hi
static __device__ __half g_al[3][M_TOT * Dm];   // projected Q lo ([1],[2] unused)
static __device__ __half g_ch[M_TOT * Dm];      // ctx hi
static __device__ __half g_cl[M_TOT * Dm];      // ctx lo

// ---------------------------------------------------------------------------
// helpers
// ---------------------------------------------------------------------------
__device__ __forceinline__ uint32_t smem_to_u32(const void* p) {
    uint32_t a;
    asm("{ .reg .u64 t; cvta.to.shared.u64 t, %1; cvt.u32.u64 %0, t; }"
        : "=r"(a) : "l"(p));
    return a;
}
__device__ __forceinline__ void cp16(uint32_t dst, const void* src) {
    asm volatile("cp.async.cg.shared.global [%0], [%1], 16;"
        :: "r"(dst), "l"(src));
}
#define CP_COMMIT() asm volatile("cp.async.commit_group;" ::: "memory")
#define CP_WAIT(n)  asm volatile("cp.async.wait_group %0;" :: "n"(n) : "memory")

__device__ __forceinline__ void ldsm_x4(uint32_t* r, uint32_t addr) {
    asm volatile("ldmatrix.sync.aligned.m8n8.x4.shared.b16 {%0,%1,%2,%3}, [%4];"
        : "=r"(r[0]), "=r"(r[1]), "=r"(r[2]), "=r"(r[3]) : "r"(addr));
}
__device__ __forceinline__ void ldsm_x4_t(uint32_t* r, uint32_t addr) {
    asm volatile("ldmatrix.sync.aligned.m8n8.x4.trans.shared.b16 {%0,%1,%2,%3}, [%4];"
        : "=r"(r[0]), "=r"(r[1]), "=r"(r[2]), "=r"(r[3]) : "r"(addr));
}
// D += A(f16 m16k16) * B(f16 k16n8), fp32 accumulate
__device__ __forceinline__ void mma_f16(float* d, const uint32_t* a, const uint32_t* b) {
    asm volatile("mma.sync.aligned.m16n8k16.row.col.f32.f16.f16.f32 "
        "{%0,%1,%2,%3}, {%4,%5,%6,%7}, {%8,%9}, {%0,%1,%2,%3};"
        : "+f"(d[0]), "+f"(d[1]), "+f"(d[2]), "+f"(d[3])
        : "r"(a[0]), "r"(a[1]), "r"(a[2]), "r"(a[3]), "r"(b[0]), "r"(b[1]));
}
__device__ __forceinline__ float fexp2(float x) {
    float t = x + 12582912.0f;
    int   n = __float_as_int(t) - 0x4B400000;
    float f = x - (t - 12582912.0f);
    float p = 0.00133335581f;
    p = fmaf(p, f, 0.00961812911f);
    p = fmaf(p, f, 0.0555041087f);
    p = fmaf(p, f, 0.240226507f);
    p = fmaf(p, f, 0.693147182f);
    p = fmaf(p, f, 1.0f);
    return __int_as_float(__float_as_int(p) + (n << 23));
}
__device__ __forceinline__ uint32_t packhf(float a, float b) {
    __half2 t = __floats2half2_rn(a, b);
    return *(uint32_t*)&t;
}
__device__ __forceinline__
void store_split2h(__half* Hi, __half* Lo, size_t idx, float x, float y) {
    __half hx = __float2half_rn(x), hy = __float2half_rn(y);
    *(__half2*)(Hi + idx) = __halves2half2(hx, hy);
    __half lx = __float2half_rn(x - __half2float(hx));
    __half ly = __float2half_rn(y - __half2float(hy));
    *(__half2*)(Lo + idx) = __halves2half2(lx, ly);
}
__device__ __forceinline__
void store_hi2(__half* Hi, size_t idx, float x, float y) {
    *(__half2*)(Hi + idx) = __floats2half2_rn(x, y);
}

// ---------------------------------------------------------------------------
// elementwise fp32 -> fp16 split (inputs z=0..2 hi+lo, weights z=3..6 hi only)
// ---------------------------------------------------------------------------
struct SplitArgs {
    const float* src[7];
    __half* hi[7];
    __half* lo[7];      // null -> hi only
    int nelem[7];
};

__global__ __launch_bounds__(256)
void split_all(SplitArgs a)
{
    const int z = blockIdx.z;
    const int i = (blockIdx.x * 256 + threadIdx.x) * 4;
    if (i >= a.nelem[z]) return;
    float4 v = *(const float4*)(a.src[z] + i);
    if (a.lo[z]) {
        store_split2h(a.hi[z], a.lo[z], i,     v.x, v.y);
        store_split2h(a.hi[z], a.lo[z], i + 2, v.z, v.w);
    } else {
        store_hi2(a.hi[z], i,     v.x, v.y);
        store_hi2(a.hi[z], i + 2, v.z, v.w);
    }
}

// ---------------------------------------------------------------------------
// tensor-core GEMM: fp16 2-product (AhBh + AlBh), 256 thr / 8 warps
// (4m x 2n grid, warp tile m32 x n64), CTA tile 128x128, BK=64,
// 3-stage cp.async pipeline.  B lo is never loaded.
// Stage layout (53248B):
//   Ah@0     : 128 rows x 128B data, 144B stride (pad -> conflict-free ldsm)
//   Al@18432 : same
//   Bh@36864 : 64 rows x 256B, chunk xor (row&7) swizzle
// ---------------------------------------------------------------------------
#define GSTAGE      53248
#define GSMEM_BYTES (3 * GSTAGE)   // 156KB -> 1 CTA/SM

struct TCArgs {
    const __half* Ah[3];
    const __half* Al[3];
    const __half* Bh[3];
    const float* bias[3];
    float scale[3];
    float* Cf[3];        // fp32 output if non-null
    __half* Ch[3];       // else fp16 hi (always set)
    __half* Cl[3];       // fp16 lo (null -> hi only)
};

__device__ __forceinline__
void gemm_issue_stage(uint32_t sb, int stage,
                      const __half* Ah, const __half* Al, const __half* Bh,
                      int m0, int n0, int k0, int t)
{
    const uint32_t st = sb + stage * GSTAGE;
    {   // A: 8 threads per row (1 line per 8 threads), 4 passes
        const int c  = t & 7;
        const int r0 = t >> 3;             // 0..31
#pragma unroll
        for (int p = 0; p < 4; ++p) {
            const int row = r0 + 32 * p;
            const size_t g = (size_t)(m0 + row) * Dm + k0 + c * 8;
            cp16(st + row * 144 + c * 16,         Ah + g);
            cp16(st + 18432 + row * 144 + c * 16, Al + g);
        }
    }
    {   // B (hi only): 16 threads per row, 4 passes
        const int c  = t & 15;
        const int r0 = t >> 4;             // 0..15
#pragma unroll
        for (int p = 0; p < 4; ++p) {
            const int row = r0 + 16 * p;
            const size_t g = (size_t)(k0 + row) * Dm + n0 + c * 8;
            cp16(st + 36864 + row * 256 + (((c ^ (row & 7))) << 4), Bh + g);
        }
    }
    CP_COMMIT();
}

__global__ __launch_bounds__(256)
void tc_gemm(TCArgs a)
{
    extern __shared__ char sm[];
    const uint32_t sb = smem_to_u32(sm);

    const int z  = blockIdx.z;
    const int m0 = blockIdx.y * 128;
    const int n0 = blockIdx.x * 128;
    const int t  = threadIdx.x;
    const int w  = t >> 5;
    const int l  = t & 31;
    const int lg = l >> 3, li = l & 7;
    const int gr = l >> 2, gc = l & 3;
    const int mw  = (w & 3) * 32;       // warp m offset (4 warps in m)
    const int nw8 = (w >> 2) * 8;       // warp n offset in n8 units (2 in n)

    const __half* Ah = a.Ah[z];
    const __half* Al = a.Al[z];
    const __half* Bh = a.Bh[z];

    float acc[2][8][4];
#pragma unroll
    for (int mi = 0; mi < 2; ++mi)
#pragma unroll
        for (int nj = 0; nj < 8; ++nj)
#pragma unroll
            for (int c = 0; c < 4; ++c) acc[mi][nj][c] = 0.0f;

    const int NS = Dm / 64;   // 12
    gemm_issue_stage(sb, 0, Ah, Al, Bh, m0, n0, 0,  t);
    gemm_issue_stage(sb, 1, Ah, Al, Bh, m0, n0, 64, t);

    int stage = 0;
    for (int s = 0; s < NS; ++s) {
        if (s + 1 < NS) { CP_WAIT(1); } else { CP_WAIT(0); }
        __syncthreads();

        if (s + 2 < NS) {
            int nst = stage + 2; if (nst >= 3) nst -= 3;
            gemm_issue_stage(sb, nst, Ah, Al, Bh, m0, n0, (s + 2) * 64, t);
        }

        const uint32_t st = sb + stage * GSTAGE;

        // A fragments: 2 m16 x 4 k16, hi+lo (144B stride, no swizzle)
        uint32_t afh[2][4][4], afl[2][4][4];
#pragma unroll
        for (int mi = 0; mi < 2; ++mi) {
            const int row = mw + mi * 16 + (lg & 1) * 8 + li;
#pragma unroll
            for (int ks = 0; ks < 4; ++ks) {
                const int c = ks * 2 + (lg >> 1);
                const uint32_t ad = st + row * 144 + c * 16;
                ldsm_x4(afh[mi][ks], ad);
                ldsm_x4(afl[mi][ks], ad + 18432);
            }
        }

        // B fragments (hi only) double-buffered over nj
        uint32_t bfh[2][2][4];
        {
            const int krow0 = lg * 8 + li;
            const int krow1 = 32 + lg * 8 + li;
            const int c = nw8;
            const uint32_t ad0 = st + 36864 + krow0 * 256 + (((c ^ (krow0 & 7))) << 4);
            const uint32_t ad1 = st + 36864 + krow1 * 256 + (((c ^ (krow1 & 7))) << 4);
            ldsm_x4_t(bfh[0][0], ad0);
            ldsm_x4_t(bfh[0][1], ad1);
        }

#pragma unroll
        for (int nj = 0; nj < 8; ++nj) {
            const int cb = nj & 1;
            if (nj < 7) {
                const int nb = cb ^ 1;
                const int c = nw8 + nj + 1;
                const int krow0 = lg * 8 + li;
                const int krow1 = 32 + lg * 8 + li;
                const uint32_t ad0 = st + 36864 + krow0 * 256 + (((c ^ (krow0 & 7))) << 4);
                const uint32_t ad1 = st + 36864 + krow1 * 256 + (((c ^ (krow1 & 7))) << 4);
                ldsm_x4_t(bfh[nb][0], ad0);
                ldsm_x4_t(bfh[nb][1], ad1);
            }
#pragma unroll
            for (int mi = 0; mi < 2; ++mi)
#pragma unroll
                for (int ks = 0; ks < 4; ++ks) {
                    const uint32_t* b2h = bfh[cb][ks >> 1] + 2 * (ks & 1);
                    mma_f16(acc[mi][nj], afh[mi][ks], b2h);
                    mma_f16(acc[mi][nj], afl[mi][ks], b2h);
                }
        }
        if (++stage == 3) stage = 0;
    }

    // epilogue
    const float* bias = a.bias[z];
    const float  scl  = a.scale[z];
    float* Cf = a.Cf[z];
    __half* Ch = a.Ch[z];
    __half* Cl = a.Cl[z];

#pragma unroll
    for (int mi = 0; mi < 2; ++mi) {
        const int row0 = m0 + mw + mi * 16 + gr;
#pragma unroll
        for (int nj = 0; nj < 8; ++nj) {
            const int col = n0 + (nw8 + nj) * 8 + gc * 2;
            const float b0 = bias[col], b1 = bias[col + 1];
            const float v00 = (acc[mi][nj][0] + b0) * scl;
            const float v01 = (acc[mi][nj][1] + b1) * scl;
            const float v10 = (acc[mi][nj][2] + b0) * scl;
            const float v11 = (acc[mi][nj][3] + b1) * scl;
            if (Cf) {
                *(float2*)&Cf[(size_t)row0 * Dm + col]       = make_float2(v00, v01);
                *(float2*)&Cf[(size_t)(row0 + 8) * Dm + col] = make_float2(v10, v11);
            } else if (Cl) {
                store_split2h(Ch, Cl, (size_t)row0 * Dm + col,       v00, v01);
                store_split2h(Ch, Cl, (size_t)(row0 + 8) * Dm + col, v10, v11);
            } else {
                store_hi2(Ch, (size_t)row0 * Dm + col,       v00, v01);
                store_hi2(Ch, (size_t)(row0 + 8) * Dm + col, v10, v11);
            }
        }
    }
}

// ---------------------------------------------------------------------------
// mma.sync flash attention, fp16 2-product:
//   S = Qh K^T + Ql K^T   (K hi only)
//   O = Ph V + Pl V       (V hi only)
// BM=128 queries, 4 warps (m32 each), BN=64, cp.async 2-stage K/V pipeline.
// Stage (16KB): Kh@0, Vh@8192; stage1 at +16384.  Q staged hi@0/lo@16384.
// ---------------------------------------------------------------------------
#define AT_SMEM_BYTES 32768

__device__ __forceinline__
void attn_issue_tile(uint32_t dst, const __half* src, int row0, int t)
{
    const int c  = t & 7;
    const int r0 = t >> 3;   // 0..15
#pragma unroll
    for (int p = 0; p < 4; ++p) {
        const int row = r0 + 16 * p;
        cp16(dst + row * 128 + (((c ^ (row & 7))) << 4),
             src + (size_t)(row0 + row) * Dm + c * 8);
    }
}

__global__ __launch_bounds__(128, 2)
void attn_mma()
{
    extern __shared__ char sm[];
    const uint32_t sb = smem_to_u32(sm);

    const int t  = threadIdx.x;
    const int w  = t >> 5;
    const int l  = t & 31;
    const int lg = l >> 3;
    const int li = l & 7;
    const int gr = l >> 2;
    const int gc = l & 3;

    const int bh = blockIdx.y;
    const int b  = bh / NH;
    const int h  = bh % NH;
    const int q0 = blockIdx.x * 128;

    const size_t hb = (size_t)b * SEQ * Dm + h * DH;
    const __half* Qh = g_ah[0] + hb;
    const __half* Ql = g_al[0] + hb;
    const __half* Kh = g_ah[1] + hb;
    const __half* Vh = g_ah[2] + hb;

    // ---- stage Q tile (128 rows x 64 f16, hi+lo = 32KB) ----
    {
        const int c  = t & 7;
        const int r0 = t >> 3;   // 0..15
#pragma unroll
        for (int p = 0; p < 8; ++p) {
            const int row = r0 + 16 * p;
            const size_t g = (size_t)(q0 + row) * Dm + c * 8;
            const uint32_t d = sb + row * 128 + (((c ^ (row & 7))) << 4);
            cp16(d,         Qh + g);
            cp16(d + 16384, Ql + g);
        }
    }
    CP_COMMIT();
    CP_WAIT(0);
    __syncthreads();

    uint32_t qfh[2][4][4], qfl[2][4][4];   // [mi][ks][4]
#pragma unroll
    for (int mi = 0; mi < 2; ++mi) {
        const int row = w * 32 + mi * 16 + (lg & 1) * 8 + li;
        const int rs  = row & 7;
#pragma unroll
        for (int ks = 0; ks < 4; ++ks) {
            const int chunk = ks * 2 + (lg >> 1);
            const uint32_t a = sb + row * 128 + (((chunk ^ rs)) << 4);
            ldsm_x4(qfh[mi][ks], a);
            ldsm_x4(qfl[mi][ks], a + 16384);
        }
    }
    __syncthreads();   // Q frags read before KV tile 0 overwrites stage 0

    // prefetch KV tile 0 into stage 0
    attn_issue_tile(sb,        Kh, 0, t);
    attn_issue_tile(sb + 8192, Vh, 0, t);
    CP_COMMIT();

    float O[2][8][4];
#pragma unroll
    for (int mi = 0; mi < 2; ++mi)
#pragma unroll
        for (int i = 0; i < 8; ++i)
#pragma unroll
            for (int j = 0; j < 4; ++j) O[mi][i][j] = 0.0f;
    float lsumA[2] = {0.f, 0.f}, lsumB[2] = {0.f, 0.f};

    const int NT = SEQ / 64;   // 32

    for (int kt = 0; kt < NT; ++kt) {
        const int cur = kt & 1;
        CP_WAIT(0);
        __syncthreads();

        if (kt + 1 < NT) {
            const uint32_t nst = sb + (cur ^ 1) * 16384;
            const int r0 = (kt + 1) * 64;
            attn_issue_tile(nst,        Kh, r0, t);
            attn_issue_tile(nst + 8192, Vh, r0, t);
            CP_COMMIT();
        }

        const uint32_t st = sb + cur * 16384;

        // ---- S = (Qh + Ql) @ Kh^T for both m16 halves ----
        float S[2][8][4];
#pragma unroll
        for (int mi = 0; mi < 2; ++mi)
#pragma unroll
            for (int i = 0; i < 8; ++i)
#pragma unroll
                for (int j = 0; j < 4; ++j) S[mi][i][j] = 0.0f;

#pragma unroll
        for (int j = 0; j < 8; ++j) {
            const int krow = 8 * j + li;
            const int ksw  = krow & 7;
#pragma unroll
            for (int kh = 0; kh < 2; ++kh) {
                uint32_t bf[4];
                const uint32_t addr =
                    st + krow * 128 + ((((kh * 4 + lg) ^ ksw)) << 4);
                ldsm_x4(bf, addr);
#pragma unroll
                for (int k2 = 0; k2 < 2; ++k2) {
                    const int ks = kh * 2 + k2;
#pragma unroll
                    for (int mi = 0; mi < 2; ++mi) {
                        mma_f16(S[mi][j], qfh[mi][ks], bf + 2 * k2);
                        mma_f16(S[mi][j], qfl[mi][ks], bf + 2 * k2);
                    }
                }
            }
        }

        // ---- P = exp2(S), pack fp16 hi/lo A-fragments ----
        uint32_t pfh[2][4][4], pfl[2][4][4];
#pragma unroll
        for (int mi = 0; mi < 2; ++mi) {
#pragma unroll
            for (int j2 = 0; j2 < 4; ++j2) {
                float* c0 = S[mi][2 * j2];
                float* c1 = S[mi][2 * j2 + 1];
                float e00 = fexp2(c0[0]), e01 = fexp2(c0[1]);
                float e02 = fexp2(c0[2]), e03 = fexp2(c0[3]);
                float e10 = fexp2(c1[0]), e11 = fexp2(c1[1]);
                float e12 = fexp2(c1[2]), e13 = fexp2(c1[3]);
                lsumA[mi] += (e00 + e01) + (e10 + e11);
                lsumB[mi] += (e02 + e03) + (e12 + e13);

                pfh[mi][j2][0] = packhf(e00, e01);
                pfh[mi][j2][1] = packhf(e02, e03);
                pfh[mi][j2][2] = packhf(e10, e11);
                pfh[mi][j2][3] = packhf(e12, e13);

                float h00 = __half2float(__float2half_rn(e00));
                float h01 = __half2float(__float2half_rn(e01));
                float h02 = __half2float(__float2half_rn(e02));
                float h03 = __half2float(__float2half_rn(e03));
                float h10 = __half2float(__float2half_rn(e10));
                float h11 = __half2float(__float2half_rn(e11));
                float h12 = __half2float(__float2half_rn(e12));
                float h13 = __half2float(__float2half_rn(e13));
                pfl[mi][j2][0] = packhf(e00 - h00, e01 - h01);
                pfl[mi][j2][1] = packhf(e02 - h02, e03 - h03);
                pfl[mi][j2][2] = packhf(e10 - h10, e11 - h11);
                pfl[mi][j2][3] = packhf(e12 - h12, e13 - h13);
            }
        }

        // ---- O += (Ph + Pl) @ Vh ----
#pragma unroll
        for (int nj = 0; nj < 8; ++nj) {
#pragma unroll
            for (int khf = 0; khf < 2; ++khf) {
                const int key = khf * 32 + lg * 8 + li;
                const uint32_t addr =
                    st + 8192 + key * 128 + (((nj ^ (key & 7))) << 4);
                uint32_t vf[4];
                ldsm_x4_t(vf, addr);
#pragma unroll
                for (int k2 = 0; k2 < 2; ++k2) {
                    const int j2 = khf * 2 + k2;
#pragma unroll
                    for (int mi = 0; mi < 2; ++mi) {
                        mma_f16(O[mi][nj], pfh[mi][j2], vf + 2 * k2);
                        mma_f16(O[mi][nj], pfl[mi][j2], vf + 2 * k2);
                    }
                }
            }
        }
    }

    // ---- normalize & store (ctx as fp16 hi/lo) ----
#pragma unroll
    for (int mi = 0; mi < 2; ++mi) {
        lsumA[mi] += __shfl_xor_sync(0xffffffffu, lsumA[mi], 1);
        lsumA[mi] += __shfl_xor_sync(0xffffffffu, lsumA[mi], 2);
        lsumB[mi] += __shfl_xor_sync(0xffffffffu, lsumB[mi], 1);
        lsumB[mi] += __shfl_xor_sync(0xffffffffu, lsumB[mi], 2);
        const float invA = 1.0f / lsumA[mi];
        const float invB = 1.0f / lsumB[mi];

        const int rowA = b * SEQ + q0 + w * 32 + mi * 16 + gr;
        const int colb = h * DH + gc * 2;
#pragma unroll
        for (int nj = 0; nj < 8; ++nj) {
            const int col = colb + nj * 8;
            store_split2h(g_ch, g_cl, (size_t)rowA * Dm + col,
                          O[mi][nj][0] * invA, O[mi][nj][1] * invA);
            store_split2h(g_ch, g_cl, (size_t)(rowA + 8) * Dm + col,
                          O[mi][nj][2] * invB, O[mi][nj][3] * invB);
        }
    }
}

// ---------------------------------------------------------------------------
// launch
// ---------------------------------------------------------------------------
extern "C" void kernel_launch(void* const* d_in, const int* in_sizes, int n_in,
                              void* d_out, int out_size)
{
    const float* v  = (const float*)d_in[0];
    const float* k  = (const float*)d_in[1];
    const float* q  = (const float*)d_in[2];
    const float* wq = (const float*)d_in[3];
    const float* bq = (const float*)d_in[4];
    const float* wk = (const float*)d_in[5];
    const float* bk = (const float*)d_in[6];
    const float* wv = (const float*)d_in[7];
    const float* bv = (const float*)d_in[8];
    const float* wo = (const float*)d_in[9];
    const float* bo = (const float*)d_in[10];
    float* out = (float*)d_out;

    __half *inh, *inl, *wh, *ah, *al, *ch, *cl;
    cudaGetSymbolAddress((void**)&inh, g_inh);
    cudaGetSymbolAddress((void**)&inl, g_inl);
    cudaGetSymbolAddress((void**)&wh,  g_wh);
    cudaGetSymbolAddress((void**)&ah,  g_ah);
    cudaGetSymbolAddress((void**)&al,  g_al);
    cudaGetSymbolAddress((void**)&ch,  g_ch);
    cudaGetSymbolAddress((void**)&cl,  g_cl);

    cudaFuncSetAttribute(tc_gemm,
                         cudaFuncAttributeMaxDynamicSharedMemorySize,
                         GSMEM_BYTES);
    cudaFuncSetAttribute(attn_mma,
                         cudaFuncAttributeMaxDynamicSharedMemorySize,
                         AT_SMEM_BYTES);

    const int ISZ = M_TOT * Dm;   // 3145728
    const int WSZ = Dm * Dm;      // 589824
    const float SCLQ = 0.18033688011112042f;   // log2(e)/8

    // 1) split inputs (hi+lo) and weights (hi only) to fp16
    SplitArgs sa;
    sa.src[0] = q;  sa.hi[0] = inh + 0 * (size_t)ISZ; sa.lo[0] = inl + 0 * (size_t)ISZ; sa.nelem[0] = ISZ;
    sa.src[1] = k;  sa.hi[1] = inh + 1 * (size_t)ISZ; sa.lo[1] = inl + 1 * (size_t)ISZ; sa.nelem[1] = ISZ;
    sa.src[2] = v;  sa.hi[2] = inh + 2 * (size_t)ISZ; sa.lo[2] = inl + 2 * (size_t)ISZ; sa.nelem[2] = ISZ;
    sa.src[3] = wq; sa.hi[3] = wh + 0 * (size_t)WSZ;  sa.lo[3] = nullptr; sa.nelem[3] = WSZ;
    sa.src[4] = wk; sa.hi[4] = wh + 1 * (size_t)WSZ;  sa.lo[4] = nullptr; sa.nelem[4] = WSZ;
    sa.src[5] = wv; sa.hi[5] = wh + 2 * (size_t)WSZ;  sa.lo[5] = nullptr; sa.nelem[5] = WSZ;
    sa.src[6] = wo; sa.hi[6] = wh + 3 * (size_t)WSZ;  sa.lo[6] = nullptr; sa.nelem[6] = WSZ;
    split_all<<<dim3(ISZ / 1024, 1, 7), 256>>>(sa);

    // 2) QKV projections (Q: hi+lo out, pre-scaled; K,V: hi only)
    TCArgs ga;
    for (int z = 0; z < 3; ++z) {
        ga.Ah[z] = inh + (size_t)z * ISZ;  ga.Al[z] = inl + (size_t)z * ISZ;
        ga.Bh[z] = wh + (size_t)z * WSZ;
        ga.Cf[z] = nullptr;
        ga.Ch[z] = ah + (size_t)z * ISZ;
        ga.Cl[z] = (z == 0) ? (al + 0 * (size_t)ISZ) : nullptr;
    }
    ga.bias[0] = bq; ga.bias[1] = bk; ga.bias[2] = bv;
    ga.scale[0] = SCLQ; ga.scale[1] = 1.0f; ga.scale[2] = 1.0f;
    tc_gemm<<<dim3(Dm / 128, M_TOT / 128, 3), 256, GSMEM_BYTES>>>(ga);

    // 3) attention (BM=128)
    attn_mma<<<dim3(SEQ / 128, BATCH * NH), 128, AT_SMEM_BYTES>>>();

    // 4) output projection -> fp32 d_out
    TCArgs go;
    for (int z = 0; z < 3; ++z) {
        go.Ah[z] = ch; go.Al[z] = cl;
        go.Bh[z] = wh + 3 * (size_t)WSZ;
        go.bias[z] = bo; go.scale[z] = 1.0f;
        go.Cf[z] = out; go.Ch[z] = nullptr; go.Cl[z] = nullptr;
    }
    tc_gemm<<<dim3(Dm / 128, M_TOT / 128, 1), 256, GSMEM_BYTES>>>(go);
}

// round 12
// speedup vs baseline: 1.7077x; 1.2197x over previous
#include <cuda_runtime.h>
#include <cuda_fp16.h>
#include <math.h>
#include <stdint.h>

#define Dm      768
#define NH      12
#define DH      64
#define BATCH   2
#define SEQ     2048
#define M_TOT   (BATCH * SEQ)   // 4096

// ---------------------------------------------------------------------------
// scratch (allocation-free rule: __device__ globals)
// ---------------------------------------------------------------------------
static __device__ __half g_inh[3][M_TOT * Dm];  // raw q,k,v hi
static __device__ __half g_inl[3][M_TOT * Dm];  // raw q,k,v lo
static __device__ __half g_wh[4][Dm * Dm];      // wq,wk,wv,wo hi (no lo)
static __device__ __half g_ah[3][M_TOT * Dm];   // projected Q,K,V hi
static __device__ __half g_al[3][M_TOT * Dm];   // projected Q lo ([1],[2] unused)
static __device__ __half g_ch[M_TOT * Dm];      // ctx hi (lo dropped)

// ---------------------------------------------------------------------------
// helpers
// ---------------------------------------------------------------------------
__device__ __forceinline__ uint32_t smem_to_u32(const void* p) {
    uint32_t a;
    asm("{ .reg .u64 t; cvta.to.shared.u64 t, %1; cvt.u32.u64 %0, t; }"
        : "=r"(a) : "l"(p));
    return a;
}
__device__ __forceinline__ void cp16(uint32_t dst, const void* src) {
    asm volatile("cp.async.cg.shared.global [%0], [%1], 16;"
        :: "r"(dst), "l"(src));
}
#define CP_COMMIT() asm volatile("cp.async.commit_group;" ::: "memory")
#define CP_WAIT(n)  asm volatile("cp.async.wait_group %0;" :: "n"(n) : "memory")

__device__ __forceinline__ void ldsm_x4(uint32_t* r, uint32_t addr) {
    asm volatile("ldmatrix.sync.aligned.m8n8.x4.shared.b16 {%0,%1,%2,%3}, [%4];"
        : "=r"(r[0]), "=r"(r[1]), "=r"(r[2]), "=r"(r[3]) : "r"(addr));
}
__device__ __forceinline__ void ldsm_x4_t(uint32_t* r, uint32_t addr) {
    asm volatile("ldmatrix.sync.aligned.m8n8.x4.trans.shared.b16 {%0,%1,%2,%3}, [%4];"
        : "=r"(r[0]), "=r"(r[1]), "=r"(r[2]), "=r"(r[3]) : "r"(addr));
}
__device__ __forceinline__ void mma_f16(float* d, const uint32_t* a, const uint32_t* b) {
    asm volatile("mma.sync.aligned.m16n8k16.row.col.f32.f16.f16.f32 "
        "{%0,%1,%2,%3}, {%4,%5,%6,%7}, {%8,%9}, {%0,%1,%2,%3};"
        : "+f"(d[0]), "+f"(d[1]), "+f"(d[2]), "+f"(d[3])
        : "r"(a[0]), "r"(a[1]), "r"(a[2]), "r"(a[3]), "r"(b[0]), "r"(b[1]));
}
__device__ __forceinline__ float fexp2(float x) {
    float t = x + 12582912.0f;
    int   n = __float_as_int(t) - 0x4B400000;
    float f = x - (t - 12582912.0f);
    float p = 0.00133335581f;
    p = fmaf(p, f, 0.00961812911f);
    p = fmaf(p, f, 0.0555041087f);
    p = fmaf(p, f, 0.240226507f);
    p = fmaf(p, f, 0.693147182f);
    p = fmaf(p, f, 1.0f);
    return __int_as_float(__float_as_int(p) + (n << 23));
}
__device__ __forceinline__ uint32_t packhf(float a, float b) {
    __half2 t = __floats2half2_rn(a, b);
    return *(uint32_t*)&t;
}
__device__ __forceinline__
void store_split2h(__half* Hi, __half* Lo, size_t idx, float x, float y) {
    __half hx = __float2half_rn(x), hy = __float2half_rn(y);
    *(__half2*)(Hi + idx) = __halves2half2(hx, hy);
    __half lx = __float2half_rn(x - __half2float(hx));
    __half ly = __float2half_rn(y - __half2float(hy));
    *(__half2*)(Lo + idx) = __halves2half2(lx, ly);
}
__device__ __forceinline__
void store_hi2(__half* Hi, size_t idx, float x, float y) {
    *(__half2*)(Hi + idx) = __floats2half2_rn(x, y);
}

// ---------------------------------------------------------------------------
// elementwise fp32 -> fp16 split (inputs z=0..2 hi+lo, weights z=3..6 hi only)
// ---------------------------------------------------------------------------
struct SplitArgs {
    const float* src[7];
    __half* hi[7];
    __half* lo[7];      // null -> hi only
    int nelem[7];
};

__global__ __launch_bounds__(256)
void split_all(SplitArgs a)
{
    const int z = blockIdx.z;
    const int i = (blockIdx.x * 256 + threadIdx.x) * 4;
    if (i >= a.nelem[z]) return;
    float4 v = *(const float4*)(a.src[z] + i);
    if (a.lo[z]) {
        store_split2h(a.hi[z], a.lo[z], i,     v.x, v.y);
        store_split2h(a.hi[z], a.lo[z], i + 2, v.z, v.w);
    } else {
        store_hi2(a.hi[z], i,     v.x, v.y);
        store_hi2(a.hi[z], i + 2, v.z, v.w);
    }
}

// ---------------------------------------------------------------------------
// tensor-core GEMM, templated on product count.
// NPROD=2: C = (Ah+Al) @ Bh ;  NPROD=1: C = Ah @ Bh.
// 256 thr / 8 warps (4m x 2n, warp tile m32 x n64), CTA 128x128, BK=64,
// 3-stage cp.async pipeline, coalesced loaders (R9-verified addressing).
// Stage layout: Ah@0 (128 rows x 144B stride), [Al@18432], Bh@NPROD*18432
//               (64 rows x 256B, chunk xor (row&7)).
// ---------------------------------------------------------------------------
template<int NPROD> struct GCfg {
    static constexpr int BOFF   = NPROD * 18432;
    static constexpr int GSTAGE = NPROD * 18432 + 16384;
    static constexpr int SMEM   = 3 * GSTAGE;
};

struct TCArgs {
    const __half* Ah[3];
    const __half* Al[3];
    const __half* Bh[3];
    const float* bias[3];
    float scale[3];
    float* Cf[3];        // fp32 output if non-null
    __half* Ch[3];       // else fp16 hi (always set)
    __half* Cl[3];       // fp16 lo (null -> hi only)
};

template<int NPROD>
__device__ __forceinline__
void gemm_issue_stage(uint32_t sb, int stage,
                      const __half* Ah, const __half* Al, const __half* Bh,
                      int m0, int n0, int k0, int t)
{
    const uint32_t st = sb + stage * GCfg<NPROD>::GSTAGE;
    {   // A: 8 threads per row (1 line per 8 threads), 4 passes
        const int c  = t & 7;
        const int r0 = t >> 3;             // 0..31
#pragma unroll
        for (int p = 0; p < 4; ++p) {
            const int row = r0 + 32 * p;
            const size_t g = (size_t)(m0 + row) * Dm + k0 + c * 8;
            cp16(st + row * 144 + c * 16, Ah + g);
            if (NPROD == 2)
                cp16(st + 18432 + row * 144 + c * 16, Al + g);
        }
    }
    {   // B (hi only): 16 threads per row, 4 passes
        const int c  = t & 15;
        const int r0 = t >> 4;             // 0..15
#pragma unroll
        for (int p = 0; p < 4; ++p) {
            const int row = r0 + 16 * p;
            const size_t g = (size_t)(k0 + row) * Dm + n0 + c * 8;
            cp16(st + GCfg<NPROD>::BOFF + row * 256 + (((c ^ (row & 7))) << 4),
                 Bh + g);
        }
    }
    CP_COMMIT();
}

template<int NPROD>
__global__ __launch_bounds__(256)
void tc_gemm(TCArgs a)
{
    extern __shared__ char sm[];
    const uint32_t sb = smem_to_u32(sm);

    const int z  = blockIdx.z;
    const int m0 = blockIdx.y * 128;
    const int n0 = blockIdx.x * 128;
    const int t  = threadIdx.x;
    const int w  = t >> 5;
    const int l  = t & 31;
    const int lg = l >> 3, li = l & 7;
    const int gr = l >> 2, gc = l & 3;
    const int mw  = (w & 3) * 32;
    const int nw8 = (w >> 2) * 8;

    const __half* Ah = a.Ah[z];
    const __half* Al = a.Al[z];
    const __half* Bh = a.Bh[z];

    float acc[2][8][4];
#pragma unroll
    for (int mi = 0; mi < 2; ++mi)
#pragma unroll
        for (int nj = 0; nj < 8; ++nj)
#pragma unroll
            for (int c = 0; c < 4; ++c) acc[mi][nj][c] = 0.0f;

    const int NS = Dm / 64;   // 12
    gemm_issue_stage<NPROD>(sb, 0, Ah, Al, Bh, m0, n0, 0,  t);
    gemm_issue_stage<NPROD>(sb, 1, Ah, Al, Bh, m0, n0, 64, t);

    int stage = 0;
    for (int s = 0; s < NS; ++s) {
        if (s + 1 < NS) { CP_WAIT(1); } else { CP_WAIT(0); }
        __syncthreads();

        if (s + 2 < NS) {
            int nst = stage + 2; if (nst >= 3) nst -= 3;
            gemm_issue_stage<NPROD>(sb, nst, Ah, Al, Bh, m0, n0, (s + 2) * 64, t);
        }

        const uint32_t st = sb + stage * GCfg<NPROD>::GSTAGE;

        // A fragments: 2 m16 x 4 k16 (144B stride, no swizzle)
        uint32_t afh[2][4][4], afl[2][4][4];
#pragma unroll
        for (int mi = 0; mi < 2; ++mi) {
            const int row = mw + mi * 16 + (lg & 1) * 8 + li;
#pragma unroll
            for (int ks = 0; ks < 4; ++ks) {
                const int c = ks * 2 + (lg >> 1);
                const uint32_t ad = st + row * 144 + c * 16;
                ldsm_x4(afh[mi][ks], ad);
                if (NPROD == 2) ldsm_x4(afl[mi][ks], ad + 18432);
            }
        }

        // B fragments double-buffered over nj
        uint32_t bfh[2][2][4];
        {
            const int krow0 = lg * 8 + li;
            const int krow1 = 32 + lg * 8 + li;
            const int c = nw8;
            const uint32_t ad0 = st + GCfg<NPROD>::BOFF + krow0 * 256 + (((c ^ (krow0 & 7))) << 4);
            const uint32_t ad1 = st + GCfg<NPROD>::BOFF + krow1 * 256 + (((c ^ (krow1 & 7))) << 4);
            ldsm_x4_t(bfh[0][0], ad0);
            ldsm_x4_t(bfh[0][1], ad1);
        }

#pragma unroll
        for (int nj = 0; nj < 8; ++nj) {
            const int cb = nj & 1;
            if (nj < 7) {
                const int nb = cb ^ 1;
                const int c = nw8 + nj + 1;
                const int krow0 = lg * 8 + li;
                const int krow1 = 32 + lg * 8 + li;
                const uint32_t ad0 = st + GCfg<NPROD>::BOFF + krow0 * 256 + (((c ^ (krow0 & 7))) << 4);
                const uint32_t ad1 = st + GCfg<NPROD>::BOFF + krow1 * 256 + (((c ^ (krow1 & 7))) << 4);
                ldsm_x4_t(bfh[nb][0], ad0);
                ldsm_x4_t(bfh[nb][1], ad1);
            }
#pragma unroll
            for (int mi = 0; mi < 2; ++mi)
#pragma unroll
                for (int ks = 0; ks < 4; ++ks) {
                    const uint32_t* b2h = bfh[cb][ks >> 1] + 2 * (ks & 1);
                    mma_f16(acc[mi][nj], afh[mi][ks], b2h);
                    if (NPROD == 2) mma_f16(acc[mi][nj], afl[mi][ks], b2h);
                }
        }
        if (++stage == 3) stage = 0;
    }

    // epilogue
    const float* bias = a.bias[z];
    const float  scl  = a.scale[z];
    float* Cf = a.Cf[z];
    __half* Ch = a.Ch[z];
    __half* Cl = a.Cl[z];

#pragma unroll
    for (int mi = 0; mi < 2; ++mi) {
        const int row0 = m0 + mw + mi * 16 + gr;
#pragma unroll
        for (int nj = 0; nj < 8; ++nj) {
            const int col = n0 + (nw8 + nj) * 8 + gc * 2;
            const float b0 = bias[col], b1 = bias[col + 1];
            const float v00 = (acc[mi][nj][0] + b0) * scl;
            const float v01 = (acc[mi][nj][1] + b1) * scl;
            const float v10 = (acc[mi][nj][2] + b0) * scl;
            const float v11 = (acc[mi][nj][3] + b1) * scl;
            if (Cf) {
                *(float2*)&Cf[(size_t)row0 * Dm + col]       = make_float2(v00, v01);
                *(float2*)&Cf[(size_t)(row0 + 8) * Dm + col] = make_float2(v10, v11);
            } else if (Cl) {
                store_split2h(Ch, Cl, (size_t)row0 * Dm + col,       v00, v01);
                store_split2h(Ch, Cl, (size_t)(row0 + 8) * Dm + col, v10, v11);
            } else {
                store_hi2(Ch, (size_t)row0 * Dm + col,       v00, v01);
                store_hi2(Ch, (size_t)(row0 + 8) * Dm + col, v10, v11);
            }
        }
    }
}

// ---------------------------------------------------------------------------
// mma.sync flash attention:
//   S = (Qh + Ql) @ Kh^T   (2-product: exp amplifies logit error)
//   O = Ph @ Vh            (1-product: P fp16 rounding enters ctx linearly)
// BM=128 queries, 4 warps (m32 each), BN=64, cp.async 2-stage K/V pipeline.
// Stage (16KB): Kh@0, Vh@8192; stage1 at +16384.  Q staged hi@0/lo@16384.
// ---------------------------------------------------------------------------
#define AT_SMEM_BYTES 32768

__device__ __forceinline__
void attn_issue_tile(uint32_t dst, const __half* src, int row0, int t)
{
    const int c  = t & 7;
    const int r0 = t >> 3;   // 0..15
#pragma unroll
    for (int p = 0; p < 4; ++p) {
        const int row = r0 + 16 * p;
        cp16(dst + row * 128 + (((c ^ (row & 7))) << 4),
             src + (size_t)(row0 + row) * Dm + c * 8);
    }
}

__global__ __launch_bounds__(128, 2)
void attn_mma()
{
    extern __shared__ char sm[];
    const uint32_t sb = smem_to_u32(sm);

    const int t  = threadIdx.x;
    const int w  = t >> 5;
    const int l  = t & 31;
    const int lg = l >> 3;
    const int li = l & 7;
    const int gr = l >> 2;
    const int gc = l & 3;

    const int bh = blockIdx.y;
    const int b  = bh / NH;
    const int h  = bh % NH;
    const int q0 = blockIdx.x * 128;

    const size_t hb = (size_t)b * SEQ * Dm + h * DH;
    const __half* Qh = g_ah[0] + hb;
    const __half* Ql = g_al[0] + hb;
    const __half* Kh = g_ah[1] + hb;
    const __half* Vh = g_ah[2] + hb;

    // ---- stage Q tile (128 rows x 64 f16, hi+lo = 32KB) ----
    {
        const int c  = t & 7;
        const int r0 = t >> 3;   // 0..15
#pragma unroll
        for (int p = 0; p < 8; ++p) {
            const int row = r0 + 16 * p;
            const size_t g = (size_t)(q0 + row) * Dm + c * 8;
            const uint32_t d = sb + row * 128 + (((c ^ (row & 7))) << 4);
            cp16(d,         Qh + g);
            cp16(d + 16384, Ql + g);
        }
    }
    CP_COMMIT();
    CP_WAIT(0);
    __syncthreads();

    uint32_t qfh[2][4][4], qfl[2][4][4];   // [mi][ks][4]
#pragma unroll
    for (int mi = 0; mi < 2; ++mi) {
        const int row = w * 32 + mi * 16 + (lg & 1) * 8 + li;
        const int rs  = row & 7;
#pragma unroll
        for (int ks = 0; ks < 4; ++ks) {
            const int chunk = ks * 2 + (lg >> 1);
            const uint32_t a = sb + row * 128 + (((chunk ^ rs)) << 4);
            ldsm_x4(qfh[mi][ks], a);
            ldsm_x4(qfl[mi][ks], a + 16384);
        }
    }
    __syncthreads();   // Q frags read before KV tile 0 overwrites stage 0

    // prefetch KV tile 0 into stage 0
    attn_issue_tile(sb,        Kh, 0, t);
    attn_issue_tile(sb + 8192, Vh, 0, t);
    CP_COMMIT();

    float O[2][8][4];
#pragma unroll
    for (int mi = 0; mi < 2; ++mi)
#pragma unroll
        for (int i = 0; i < 8; ++i)
#pragma unroll
            for (int j = 0; j < 4; ++j) O[mi][i][j] = 0.0f;
    float lsumA[2] = {0.f, 0.f}, lsumB[2] = {0.f, 0.f};

    const int NT = SEQ / 64;   // 32

    for (int kt = 0; kt < NT; ++kt) {
        const int cur = kt & 1;
        CP_WAIT(0);
        __syncthreads();

        if (kt + 1 < NT) {
            const uint32_t nst = sb + (cur ^ 1) * 16384;
            const int r0 = (kt + 1) * 64;
            attn_issue_tile(nst,        Kh, r0, t);
            attn_issue_tile(nst + 8192, Vh, r0, t);
            CP_COMMIT();
        }

        const uint32_t st = sb + cur * 16384;

        // ---- S = (Qh + Ql) @ Kh^T ----
        float S[2][8][4];
#pragma unroll
        for (int mi = 0; mi < 2; ++mi)
#pragma unroll
            for (int i = 0; i < 8; ++i)
#pragma unroll
                for (int j = 0; j < 4; ++j) S[mi][i][j] = 0.0f;

#pragma unroll
        for (int j = 0; j < 8; ++j) {
            const int krow = 8 * j + li;
            const int ksw  = krow & 7;
#pragma unroll
            for (int kh = 0; kh < 2; ++kh) {
                uint32_t bf[4];
                const uint32_t addr =
                    st + krow * 128 + ((((kh * 4 + lg) ^ ksw)) << 4);
                ldsm_x4(bf, addr);
#pragma unroll
                for (int k2 = 0; k2 < 2; ++k2) {
                    const int ks = kh * 2 + k2;
#pragma unroll
                    for (int mi = 0; mi < 2; ++mi) {
                        mma_f16(S[mi][j], qfh[mi][ks], bf + 2 * k2);
                        mma_f16(S[mi][j], qfl[mi][ks], bf + 2 * k2);
                    }
                }
            }
        }

        // ---- P = exp2(S), pack fp16 A-fragments (hi only) ----
        uint32_t pfh[2][4][4];
#pragma unroll
        for (int mi = 0; mi < 2; ++mi) {
#pragma unroll
            for (int j2 = 0; j2 < 4; ++j2) {
                float* c0 = S[mi][2 * j2];
                float* c1 = S[mi][2 * j2 + 1];
                float e00 = fexp2(c0[0]), e01 = fexp2(c0[1]);
                float e02 = fexp2(c0[2]), e03 = fexp2(c0[3]);
                float e10 = fexp2(c1[0]), e11 = fexp2(c1[1]);
                float e12 = fexp2(c1[2]), e13 = fexp2(c1[3]);
                lsumA[mi] += (e00 + e01) + (e10 + e11);
                lsumB[mi] += (e02 + e03) + (e12 + e13);

                pfh[mi][j2][0] = packhf(e00, e01);
                pfh[mi][j2][1] = packhf(e02, e03);
                pfh[mi][j2][2] = packhf(e10, e11);
                pfh[mi][j2][3] = packhf(e12, e13);
            }
        }

        // ---- O += Ph @ Vh ----
#pragma unroll
        for (int nj = 0; nj < 8; ++nj) {
#pragma unroll
            for (int khf = 0; khf < 2; ++khf) {
                const int key = khf * 32 + lg * 8 + li;
                const uint32_t addr =
                    st + 8192 + key * 128 + (((nj ^ (key & 7))) << 4);
                uint32_t vf[4];
                ldsm_x4_t(vf, addr);
#pragma unroll
                for (int k2 = 0; k2 < 2; ++k2) {
                    const int j2 = khf * 2 + k2;
#pragma unroll
                    for (int mi = 0; mi < 2; ++mi)
                        mma_f16(O[mi][nj], pfh[mi][j2], vf + 2 * k2);
                }
            }
        }
    }

    // ---- normalize & store (ctx hi only) ----
#pragma unroll
    for (int mi = 0; mi < 2; ++mi) {
        lsumA[mi] += __shfl_xor_sync(0xffffffffu, lsumA[mi], 1);
        lsumA[mi] += __shfl_xor_sync(0xffffffffu, lsumA[mi], 2);
        lsumB[mi] += __shfl_xor_sync(0xffffffffu, lsumB[mi], 1);
        lsumB[mi] += __shfl_xor_sync(0xffffffffu, lsumB[mi], 2);
        const float invA = 1.0f / lsumA[mi];
        const float invB = 1.0f / lsumB[mi];

        const int rowA = b * SEQ + q0 + w * 32 + mi * 16 + gr;
        const int colb = h * DH + gc * 2;
#pragma unroll
        for (int nj = 0; nj < 8; ++nj) {
            const int col = colb + nj * 8;
            store_hi2(g_ch, (size_t)rowA * Dm + col,
                      O[mi][nj][0] * invA, O[mi][nj][1] * invA);
            store_hi2(g_ch, (size_t)(rowA + 8) * Dm + col,
                      O[mi][nj][2] * invB, O[mi][nj][3] * invB);
        }
    }
}

// ---------------------------------------------------------------------------
// launch
// ---------------------------------------------------------------------------
extern "C" void kernel_launch(void* const* d_in, const int* in_sizes, int n_in,
                              void* d_out, int out_size)
{
    const float* v  = (const float*)d_in[0];
    const float* k  = (const float*)d_in[1];
    const float* q  = (const float*)d_in[2];
    const float* wq = (const float*)d_in[3];
    const float* bq = (const float*)d_in[4];
    const float* wk = (const float*)d_in[5];
    const float* bk = (const float*)d_in[6];
    const float* wv = (const float*)d_in[7];
    const float* bv = (const float*)d_in[8];
    const float* wo = (const float*)d_in[9];
    const float* bo = (const float*)d_in[10];
    float* out = (float*)d_out;

    __half *inh, *inl, *wh, *ah, *al, *ch;
    cudaGetSymbolAddress((void**)&inh, g_inh);
    cudaGetSymbolAddress((void**)&inl, g_inl);
    cudaGetSymbolAddress((void**)&wh,  g_wh);
    cudaGetSymbolAddress((void**)&ah,  g_ah);
    cudaGetSymbolAddress((void**)&al,  g_al);
    cudaGetSymbolAddress((void**)&ch,  g_ch);

    cudaFuncSetAttribute(tc_gemm<2>,
                         cudaFuncAttributeMaxDynamicSharedMemorySize,
                         GCfg<2>::SMEM);
    cudaFuncSetAttribute(tc_gemm<1>,
                         cudaFuncAttributeMaxDynamicSharedMemorySize,
                         GCfg<1>::SMEM);
    cudaFuncSetAttribute(attn_mma,
                         cudaFuncAttributeMaxDynamicSharedMemorySize,
                         AT_SMEM_BYTES);

    const int ISZ = M_TOT * Dm;   // 3145728
    const int WSZ = Dm * Dm;      // 589824
    const float SCLQ = 0.18033688011112042f;   // log2(e)/8

    // 1) split inputs (hi+lo) and weights (hi only) to fp16
    SplitArgs sa;
    sa.src[0] = q;  sa.hi[0] = inh + 0 * (size_t)ISZ; sa.lo[0] = inl + 0 * (size_t)ISZ; sa.nelem[0] = ISZ;
    sa.src[1] = k;  sa.hi[1] = inh + 1 * (size_t)ISZ; sa.lo[1] = inl + 1 * (size_t)ISZ; sa.nelem[1] = ISZ;
    sa.src[2] = v;  sa.hi[2] = inh + 2 * (size_t)ISZ; sa.lo[2] = inl + 2 * (size_t)ISZ; sa.nelem[2] = ISZ;
    sa.src[3] = wq; sa.hi[3] = wh + 0 * (size_t)WSZ;  sa.lo[3] = nullptr; sa.nelem[3] = WSZ;
    sa.src[4] = wk; sa.hi[4] = wh + 1 * (size_t)WSZ;  sa.lo[4] = nullptr; sa.nelem[4] = WSZ;
    sa.src[5] = wv; sa.hi[5] = wh + 2 * (size_t)WSZ;  sa.lo[5] = nullptr; sa.nelem[5] = WSZ;
    sa.src[6] = wo; sa.hi[6] = wh + 3 * (size_t)WSZ;  sa.lo[6] = nullptr; sa.nelem[6] = WSZ;
    split_all<<<dim3(ISZ / 1024, 1, 7), 256>>>(sa);

    // 2) QKV projections (2-product; Q emits hi+lo pre-scaled, K/V hi only)
    TCArgs ga;
    for (int z = 0; z < 3; ++z) {
        ga.Ah[z] = inh + (size_t)z * ISZ;  ga.Al[z] = inl + (size_t)z * ISZ;
        ga.Bh[z] = wh + (size_t)z * WSZ;
        ga.Cf[z] = nullptr;
        ga.Ch[z] = ah + (size_t)z * ISZ;
        ga.Cl[z] = (z == 0) ? (al + 0 * (size_t)ISZ) : nullptr;
    }
    ga.bias[0] = bq; ga.bias[1] = bk; ga.bias[2] = bv;
    ga.scale[0] = SCLQ; ga.scale[1] = 1.0f; ga.scale[2] = 1.0f;
    tc_gemm<2><<<dim3(Dm / 128, M_TOT / 128, 3), 256, GCfg<2>::SMEM>>>(ga);

    // 3) attention (BM=128; PV single-product; ctx hi only)
    attn_mma<<<dim3(SEQ / 128, BATCH * NH), 128, AT_SMEM_BYTES>>>();

    // 4) output projection (1-product) -> fp32 d_out
    TCArgs go;
    for (int z = 0; z < 3; ++z) {
        go.Ah[z] = ch; go.Al[z] = nullptr;
        go.Bh[z] = wh + 3 * (size_t)WSZ;
        go.bias[z] = bo; go.scale[z] = 1.0f;
        go.Cf[z] = out; go.Ch[z] = nullptr; go.Cl[z] = nullptr;
    }
    tc_gemm<1><<<dim3(Dm / 128, M_TOT / 128, 1), 256, GCfg<1>::SMEM>>>(go);
}